// round 5
// baseline (speedup 1.0000x reference)
#include <cuda_runtime.h>
#include <cuda_bf16.h>
#include <math.h>
#include <stdint.h>

#define N_NODES 50000
#define N_EDGES 1600000
#define D 128
#define AP 68     // padded leading dim (floats) for fp32 GEMM A-tiles
#define BP 136    // padded leading dim (bf16 elems) for mma tiles: 272B = 17 x 16B units

// ---------------- device scratch (no allocations allowed) ----------------
__device__ int   g_cnt[N_NODES];
__device__ int   g_rowptr[N_NODES + 1];
__device__ int   g_cursor[N_NODES];
__device__ int   g_bsum[64];
__device__ int   g_col[2 * N_EDGES];          // 12.8 MB
__device__ float g_dinv[N_NODES];
__device__ float g_bufA[N_NODES * D];         // 25.6 MB
__device__ float g_bufB[N_NODES * D];         // 25.6 MB

// ---------------- CSR build ----------------
__global__ void zero_cnt_kernel() {
    int i = blockIdx.x * blockDim.x + threadIdx.x;
    if (i < N_NODES) g_cnt[i] = 0;
}

__global__ void count_kernel(const int* __restrict__ ei) {
    int e = blockIdx.x * blockDim.x + threadIdx.x;
    if (e < N_EDGES) {
        int a = ei[2 * e], b = ei[2 * e + 1];
        atomicAdd(&g_cnt[b], 1);
        atomicAdd(&g_cnt[a], 1);
    }
}

__global__ void dinv_kernel() {
    int i = blockIdx.x * blockDim.x + threadIdx.x;
    if (i < N_NODES) g_dinv[i] = rsqrtf((float)(g_cnt[i] + 1));  // +1 self loop
}

__global__ void scan_block_kernel() {
    __shared__ int s[1024];
    int i = blockIdx.x * 1024 + threadIdx.x;
    int v = (i < N_NODES) ? g_cnt[i] : 0;
    s[threadIdx.x] = v;
    __syncthreads();
#pragma unroll
    for (int off = 1; off < 1024; off <<= 1) {
        int t = 0;
        if (threadIdx.x >= off) t = s[threadIdx.x - off];
        __syncthreads();
        if (threadIdx.x >= off) s[threadIdx.x] += t;
        __syncthreads();
    }
    if (i < N_NODES) g_rowptr[i] = s[threadIdx.x] - v;  // exclusive
    if (threadIdx.x == 1023) g_bsum[blockIdx.x] = s[1023];
}

__global__ void scan_bsum_kernel(int nb) {
    if (threadIdx.x == 0 && blockIdx.x == 0) {
        int acc = 0;
        for (int i = 0; i < nb; i++) { int v = g_bsum[i]; g_bsum[i] = acc; acc += v; }
    }
}

__global__ void scan_fix_kernel() {
    int i = blockIdx.x * blockDim.x + threadIdx.x;
    if (i < N_NODES) {
        int r = g_rowptr[i] + g_bsum[i >> 10];
        g_rowptr[i] = r;
        g_cursor[i] = r;
    }
    if (i == 0) g_rowptr[N_NODES] = 2 * N_EDGES;
}

__global__ void fill_kernel(const int* __restrict__ ei) {
    int e = blockIdx.x * blockDim.x + threadIdx.x;
    if (e < N_EDGES) {
        int a = ei[2 * e], b = ei[2 * e + 1];
        g_col[atomicAdd(&g_cursor[b], 1)] = a;   // a -> b
        g_col[atomicAdd(&g_cursor[a], 1)] = b;   // b -> a
    }
}

// ---------------- dense node GEMM: C[r] = scale[r] * (A[r] @ W) ----------------
__global__ void gemm_kernel(const float* __restrict__ A, const float* __restrict__ W,
                            float* __restrict__ C, const float* __restrict__ scale,
                            int nRows) {
    extern __shared__ float sm[];
    float* Ws = sm;              // 128*128
    float* As = sm + D * D;      // 128*AP (k-major, transposed)
    int tid = threadIdx.x;

    {
        const float4* W4 = (const float4*)W;
        float4* Ws4 = (float4*)Ws;
        for (int i = tid; i < D * D / 4; i += 256) Ws4[i] = W4[i];
    }
    __syncthreads();

    int ty = tid >> 4, tx = tid & 15;
    int ntiles = (nRows + 63) >> 6;

    for (int t = blockIdx.x; t < ntiles; t += gridDim.x) {
        __syncthreads();
        int row0 = t << 6;
        for (int i = tid; i < 64 * D; i += 256) {
            int r = i >> 7, f = i & 127;
            int row = row0 + r;
            As[f * AP + r] = (row < nRows) ? A[row * D + f] : 0.f;
        }
        __syncthreads();

        float acc[4][8];
#pragma unroll
        for (int r = 0; r < 4; r++)
#pragma unroll
            for (int c = 0; c < 8; c++) acc[r][c] = 0.f;

#pragma unroll 8
        for (int k = 0; k < D; k++) {
            float4 a  = *(const float4*)&As[k * AP + ty * 4];
            float4 w0 = *(const float4*)&Ws[k * D + tx * 8];
            float4 w1 = *(const float4*)&Ws[k * D + tx * 8 + 4];
            float av[4] = {a.x, a.y, a.z, a.w};
            float wv[8] = {w0.x, w0.y, w0.z, w0.w, w1.x, w1.y, w1.z, w1.w};
#pragma unroll
            for (int r = 0; r < 4; r++)
#pragma unroll
                for (int c = 0; c < 8; c++) acc[r][c] = fmaf(av[r], wv[c], acc[r][c]);
        }

#pragma unroll
        for (int r = 0; r < 4; r++) {
            int row = row0 + ty * 4 + r;
            if (row < nRows) {
                float s = scale ? scale[row] : 1.0f;
                float4 o0 = make_float4(acc[r][0] * s, acc[r][1] * s, acc[r][2] * s, acc[r][3] * s);
                float4 o1 = make_float4(acc[r][4] * s, acc[r][5] * s, acc[r][6] * s, acc[r][7] * s);
                *(float4*)&C[row * D + tx * 8]     = o0;
                *(float4*)&C[row * D + tx * 8 + 4] = o1;
            }
        }
    }
}

// ---------------- SpMM aggregation ----------------
__global__ void spmm_kernel(const float* __restrict__ Hs, const float* __restrict__ b,
                            float* __restrict__ fout) {
    int i = blockIdx.x;
    int tid = threadIdx.x;
    __shared__ int sc[128];
    int start = g_rowptr[i], end = g_rowptr[i + 1];

    float a0 = Hs[i * D + tid];  // self-loop term
    float a1 = 0.f, a2 = 0.f, a3 = 0.f;

    for (int base = start; base < end; base += 128) {
        int m = end - base; if (m > 128) m = 128;
        if (tid < m) sc[tid] = g_col[base + tid];
        __syncthreads();
        int j = 0;
        for (; j + 4 <= m; j += 4) {
            int c0 = sc[j], c1 = sc[j + 1], c2 = sc[j + 2], c3 = sc[j + 3];
            a0 += Hs[c0 * D + tid];
            a1 += Hs[c1 * D + tid];
            a2 += Hs[c2 * D + tid];
            a3 += Hs[c3 * D + tid];
        }
        for (; j < m; j++) a0 += Hs[sc[j] * D + tid];
        __syncthreads();
    }
    float acc = (a0 + a1) + (a2 + a3);
    fout[i * D + tid] = fmaxf(fmaf(g_dinv[i], acc, b[tid]), 0.f);
}

// ---------------- fused edge MLP (tensor-core bf16 mma) ----------------
// h1 = relu(G[s]-G[d]+bm1)  [built as bf16 in smem]
// h2 = relu(h1 @ Wm2 + bm2) [mma.sync m16n8k16 bf16 -> fp32]
// out = sigmoid(h2 . wm3 + bm3)
//
// smem byte layout:
//   Wt  : bf16[128][BP]  (Wm2 transposed: Wt[n][k] = Wm2[k][n])   34816 B
//   h1s : bf16[64][BP]                                            17408 B
//   sb1,sb2,sw3 : float[128] each                                  1536 B
//   partial : float[64][2]                                          512 B
//   ssd : int[128]                                                  512 B
#define SMEM_E_BYTES (34816 + 17408 + 3*512 + 512 + 512)

__device__ __forceinline__ void mma_bf16(float& c0, float& c1, float& c2, float& c3,
                                         uint32_t a0, uint32_t a1, uint32_t a2, uint32_t a3,
                                         uint32_t b0, uint32_t b1) {
    asm volatile(
        "mma.sync.aligned.m16n8k16.row.col.f32.bf16.bf16.f32 "
        "{%0,%1,%2,%3},{%4,%5,%6,%7},{%8,%9},{%0,%1,%2,%3};\n"
        : "+f"(c0), "+f"(c1), "+f"(c2), "+f"(c3)
        : "r"(a0), "r"(a1), "r"(a2), "r"(a3), "r"(b0), "r"(b1));
}

__device__ __forceinline__ void ldm_x4(uint32_t& r0, uint32_t& r1, uint32_t& r2, uint32_t& r3,
                                       uint32_t addr) {
    asm volatile("ldmatrix.sync.aligned.m8n8.x4.shared.b16 {%0,%1,%2,%3}, [%4];\n"
                 : "=r"(r0), "=r"(r1), "=r"(r2), "=r"(r3) : "r"(addr));
}

__global__ __launch_bounds__(256)
void edge_kernel(const float* __restrict__ G, const int* __restrict__ ei,
                 const float* __restrict__ bm1, const float* __restrict__ Wm2,
                 const float* __restrict__ bm2, const float* __restrict__ Wm3,
                 const float* __restrict__ bm3, float* __restrict__ out) {
    extern __shared__ char smraw[];
    __nv_bfloat16* Wt  = (__nv_bfloat16*)smraw;                 // 128*BP bf16
    __nv_bfloat16* h1s = (__nv_bfloat16*)(smraw + 34816);       // 64*BP bf16
    float* sb1     = (float*)(smraw + 34816 + 17408);
    float* sb2     = sb1 + 128;
    float* sw3     = sb2 + 128;
    float* partial = sw3 + 128;                                 // [64][2]
    int*   ssd     = (int*)(partial + 128);                     // 128 ints

    int tid = threadIdx.x;

    // load Wm2 transposed into smem as bf16 (coalesced global read)
    for (int i = tid; i < D * D; i += 256) {
        int k = i >> 7, n = i & 127;
        Wt[n * BP + k] = __float2bfloat16(Wm2[i]);
    }
    if (tid < 128) { sb1[tid] = bm1[tid]; sb2[tid] = bm2[tid]; sw3[tid] = Wm3[tid]; }
    __syncthreads();
    float b3 = bm3[0];

    uint32_t wt_base  = (uint32_t)__cvta_generic_to_shared(Wt);
    uint32_t h1_base  = (uint32_t)__cvta_generic_to_shared(h1s);

    int warp = tid >> 5;
    int l    = tid & 31;
    int m0    = (warp & 3) * 16;   // 4 row-groups of 16 edges
    int nbase = (warp >> 2) * 64;  // 2 col-halves of 64 outputs
    int nh    = warp >> 2;
    int grp = l >> 2, tig = l & 3;

    // precompute ldmatrix smem addresses (byte offsets added per k-step)
    uint32_t a_addr0 = h1_base + ((m0 + (l & 15)) * BP + (l >> 4) * 8) * 2;
    int lr = l & 7, g8 = l >> 3;
    uint32_t b_row = nbase + (g8 >> 1) * 8 + lr;   // + j*16 per n-pair
    uint32_t b_k0  = (g8 & 1) * 8;                 // + kb*16 per k-step

    const int ntiles = N_EDGES / 64;  // 25000 exactly

    for (int t = blockIdx.x; t < ntiles; t += gridDim.x) {
        __syncthreads();
        int e0 = t << 6;
        if (tid < 128) ssd[tid] = ei[2 * e0 + tid];
        __syncthreads();

        // build h1 tile in bf16 (2 features per thread, float2 gathers)
        for (int i = tid; i < 64 * 64; i += 256) {
            int e = i >> 6, fp = (i & 63) * 2;
            int s = ssd[2 * e], d = ssd[2 * e + 1];
            float2 gs = *(const float2*)&G[s * D + fp];
            float2 gd = *(const float2*)&G[d * D + fp];
            float v0 = fmaxf(gs.x - gd.x + sb1[fp], 0.f);
            float v1 = fmaxf(gs.y - gd.y + sb1[fp + 1], 0.f);
            *(__nv_bfloat162*)&h1s[e * BP + fp] = __floats2bfloat162_rn(v0, v1);
        }
        __syncthreads();

        float acc[8][4];
#pragma unroll
        for (int ns = 0; ns < 8; ns++)
#pragma unroll
            for (int c = 0; c < 4; c++) acc[ns][c] = 0.f;

#pragma unroll
        for (int kb = 0; kb < 8; kb++) {
            uint32_t a0, a1, a2, a3;
            ldm_x4(a0, a1, a2, a3, a_addr0 + kb * 16 * 2);
#pragma unroll
            for (int j = 0; j < 4; j++) {
                uint32_t b0, b1, b2r, b3r;
                uint32_t baddr = wt_base + ((b_row + j * 16) * BP + b_k0 + kb * 16) * 2;
                ldm_x4(b0, b1, b2r, b3r, baddr);
                mma_bf16(acc[2*j][0], acc[2*j][1], acc[2*j][2], acc[2*j][3],
                         a0, a1, a2, a3, b0, b1);
                mma_bf16(acc[2*j+1][0], acc[2*j+1][1], acc[2*j+1][2], acc[2*j+1][3],
                         a0, a1, a2, a3, b2r, b3r);
            }
        }

        // epilogue: relu + dot with wm3, reduce within quad, across col-halves
        float p0 = 0.f, p1 = 0.f;
#pragma unroll
        for (int ns = 0; ns < 8; ns++) {
            int c0 = nbase + ns * 8 + tig * 2;
            int c1 = c0 + 1;
            p0 = fmaf(fmaxf(acc[ns][0] + sb2[c0], 0.f), sw3[c0], p0);
            p0 = fmaf(fmaxf(acc[ns][1] + sb2[c1], 0.f), sw3[c1], p0);
            p1 = fmaf(fmaxf(acc[ns][2] + sb2[c0], 0.f), sw3[c0], p1);
            p1 = fmaf(fmaxf(acc[ns][3] + sb2[c1], 0.f), sw3[c1], p1);
        }
        p0 += __shfl_xor_sync(0xffffffffu, p0, 1);
        p0 += __shfl_xor_sync(0xffffffffu, p0, 2);
        p1 += __shfl_xor_sync(0xffffffffu, p1, 1);
        p1 += __shfl_xor_sync(0xffffffffu, p1, 2);
        if (tig == 0) {
            partial[(m0 + grp) * 2 + nh]     = p0;
            partial[(m0 + grp + 8) * 2 + nh] = p1;
        }
        __syncthreads();
        if (tid < 64) {
            float z = partial[tid * 2] + partial[tid * 2 + 1] + b3;
            out[e0 + tid] = 1.0f / (1.0f + expf(-z));
        }
    }
}

// ---------------- launch ----------------
extern "C" void kernel_launch(void* const* d_in, const int* in_sizes, int n_in,
                              void* d_out, int out_size) {
    const float* x   = (const float*)d_in[0];
    const int*   ei  = (const int*)d_in[1];
    const float* W1  = (const float*)d_in[2];
    const float* b1  = (const float*)d_in[3];
    const float* W2  = (const float*)d_in[4];
    const float* b2  = (const float*)d_in[5];
    const float* Wm1 = (const float*)d_in[6];
    const float* bm1 = (const float*)d_in[7];
    const float* Wm2 = (const float*)d_in[8];
    const float* bm2 = (const float*)d_in[9];
    const float* Wm3 = (const float*)d_in[10];
    const float* bm3 = (const float*)d_in[11];
    float* out = (float*)d_out;

    void *bufA, *bufB, *dinvp;
    cudaGetSymbolAddress(&bufA, g_bufA);
    cudaGetSymbolAddress(&bufB, g_bufB);
    cudaGetSymbolAddress(&dinvp, g_dinv);

    const int smemG = (D * D + D * AP) * (int)sizeof(float);
    cudaFuncSetAttribute(gemm_kernel, cudaFuncAttributeMaxDynamicSharedMemorySize, smemG);
    cudaFuncSetAttribute(edge_kernel, cudaFuncAttributeMaxDynamicSharedMemorySize, SMEM_E_BYTES);

    const int GRID  = 296;   // fp32 node GEMMs: ~2 persistent blocks/SM
    const int GRIDE = 444;   // edge kernel: 3 persistent blocks/SM

    // CSR build + degrees
    zero_cnt_kernel<<<(N_NODES + 255) / 256, 256>>>();
    count_kernel<<<(N_EDGES + 255) / 256, 256>>>(ei);
    dinv_kernel<<<(N_NODES + 255) / 256, 256>>>();
    scan_block_kernel<<<(N_NODES + 1023) / 1024, 1024>>>();
    scan_bsum_kernel<<<1, 32>>>((N_NODES + 1023) / 1024);
    scan_fix_kernel<<<(N_NODES + 255) / 256, 256>>>();
    fill_kernel<<<(N_EDGES + 255) / 256, 256>>>(ei);

    // GCN layer 1
    gemm_kernel<<<GRID, 256, smemG>>>(x, W1, (float*)bufA, (const float*)dinvp, N_NODES);
    spmm_kernel<<<N_NODES, 128>>>((const float*)bufA, b1, (float*)bufB);

    // GCN layer 2
    gemm_kernel<<<GRID, 256, smemG>>>((const float*)bufB, W2, (float*)bufA, (const float*)dinvp, N_NODES);
    spmm_kernel<<<N_NODES, 128>>>((const float*)bufA, b2, (float*)bufB);

    // G = f2 @ Wm1  (factored edge-MLP layer 1)
    gemm_kernel<<<GRID, 256, smemG>>>((const float*)bufB, Wm1, (float*)bufA, nullptr, N_NODES);

    // fused edge MLP on tensor cores
    edge_kernel<<<GRIDE, 256, SMEM_E_BYTES>>>((const float*)bufA, ei, bm1, Wm2, bm2, Wm3, bm3, out);
}

// round 7
// speedup vs baseline: 1.5682x; 1.5682x over previous
#include <cuda_runtime.h>
#include <cuda_fp16.h>
#include <math.h>
#include <stdint.h>

#define N_NODES 50000
#define N_EDGES 1600000
#define D 128
#define BP 136    // padded leading dim (half elems): 272B = 17 x 16B units, ldmatrix conflict-light

// ---------------- device scratch (no allocations allowed) ----------------
__device__ int   g_cnt[N_NODES];
__device__ int   g_rowptr[N_NODES + 1];
__device__ int   g_cursor[N_NODES];
__device__ int   g_bsum[64];
__device__ int   g_col[2 * N_EDGES];          // 12.8 MB
__device__ float g_dinv[N_NODES];
__device__ __half g_bufA[N_NODES * D];        // 12.8 MB (node features, fp16)
__device__ __half g_bufB[N_NODES * D];        // 12.8 MB

// ---------------- CSR build ----------------
__global__ void zero_cnt_kernel() {
    int i = blockIdx.x * blockDim.x + threadIdx.x;
    if (i < N_NODES) g_cnt[i] = 0;
}

__global__ void count_kernel(const int2* __restrict__ ei2) {
    int e = blockIdx.x * blockDim.x + threadIdx.x;
    if (e < N_EDGES) {
        int2 p = ei2[e];
        atomicAdd(&g_cnt[p.y], 1);
        atomicAdd(&g_cnt[p.x], 1);
    }
}

__global__ void scan_block_kernel() {
    __shared__ int s[1024];
    int i = blockIdx.x * 1024 + threadIdx.x;
    int v = (i < N_NODES) ? g_cnt[i] : 0;
    if (i < N_NODES) g_dinv[i] = rsqrtf((float)(v + 1));  // +1 self loop
    s[threadIdx.x] = v;
    __syncthreads();
#pragma unroll
    for (int off = 1; off < 1024; off <<= 1) {
        int t = 0;
        if (threadIdx.x >= off) t = s[threadIdx.x - off];
        __syncthreads();
        if (threadIdx.x >= off) s[threadIdx.x] += t;
        __syncthreads();
    }
    if (i < N_NODES) g_rowptr[i] = s[threadIdx.x] - v;  // exclusive
    if (threadIdx.x == 1023) g_bsum[blockIdx.x] = s[1023];
}

__global__ void scan_bsum_kernel(int nb) {
    if (threadIdx.x == 0 && blockIdx.x == 0) {
        int acc = 0;
        for (int i = 0; i < nb; i++) { int v = g_bsum[i]; g_bsum[i] = acc; acc += v; }
    }
}

__global__ void scan_fix_kernel() {
    int i = blockIdx.x * blockDim.x + threadIdx.x;
    if (i < N_NODES) {
        int r = g_rowptr[i] + g_bsum[i >> 10];
        g_rowptr[i] = r;
        g_cursor[i] = r;
    }
    if (i == 0) g_rowptr[N_NODES] = 2 * N_EDGES;
}

__global__ void fill_kernel(const int2* __restrict__ ei2) {
    int e = blockIdx.x * blockDim.x + threadIdx.x;
    if (e < N_EDGES) {
        int2 p = ei2[e];
        g_col[atomicAdd(&g_cursor[p.y], 1)] = p.x;   // a -> b
        g_col[atomicAdd(&g_cursor[p.x], 1)] = p.y;   // b -> a
    }
}

// ---------------- mma helpers (proven layout from edge kernel) ----------------
__device__ __forceinline__ void mma_f16(float& c0, float& c1, float& c2, float& c3,
                                        uint32_t a0, uint32_t a1, uint32_t a2, uint32_t a3,
                                        uint32_t b0, uint32_t b1) {
    asm volatile(
        "mma.sync.aligned.m16n8k16.row.col.f32.f16.f16.f32 "
        "{%0,%1,%2,%3},{%4,%5,%6,%7},{%8,%9},{%0,%1,%2,%3};\n"
        : "+f"(c0), "+f"(c1), "+f"(c2), "+f"(c3)
        : "r"(a0), "r"(a1), "r"(a2), "r"(a3), "r"(b0), "r"(b1));
}

__device__ __forceinline__ void ldm_x4(uint32_t& r0, uint32_t& r1, uint32_t& r2, uint32_t& r3,
                                       uint32_t addr) {
    asm volatile("ldmatrix.sync.aligned.m8n8.x4.shared.b16 {%0,%1,%2,%3}, [%4];\n"
                 : "=r"(r0), "=r"(r1), "=r"(r2), "=r"(r3) : "r"(addr));
}

// ---------------- tensor-core node GEMM: C[r] = scale[r] * (A[r] @ W), fp16 out ----------------
// tile 64 rows x 128 cols, 256 threads, 8 warps (4 row-groups x 2 col-halves)
#define SMEM_G_BYTES (128 * BP * 2 + 64 * BP * 2)   // Wt + As

template<int IN_HALF>
__global__ __launch_bounds__(256)
void gemm_tc_kernel(const void* __restrict__ Av, const float* __restrict__ W,
                    __half* __restrict__ C, const float* __restrict__ scale, int nRows) {
    extern __shared__ char smraw[];
    __half* Wt = (__half*)smraw;                    // [128][BP]  Wt[n][k] = W[k][n]
    __half* As = (__half*)(smraw + 128 * BP * 2);   // [64][BP]   row-major
    int tid = threadIdx.x;

    for (int i = tid; i < D * D; i += 256) {
        int k = i >> 7, n = i & 127;
        Wt[n * BP + k] = __float2half(W[i]);
    }
    __syncthreads();

    uint32_t wt_base = (uint32_t)__cvta_generic_to_shared(Wt);
    uint32_t as_base = (uint32_t)__cvta_generic_to_shared(As);

    int warp = tid >> 5, l = tid & 31;
    int m0    = (warp & 3) * 16;
    int nbase = (warp >> 2) * 64;
    uint32_t a_addr0 = as_base + ((m0 + (l & 15)) * BP + (l >> 4) * 8) * 2;
    int lr = l & 7, g8 = l >> 3;
    uint32_t b_row = nbase + (g8 >> 1) * 8 + lr;
    uint32_t b_k0  = (g8 & 1) * 8;
    int grp = l >> 2, tig = l & 3;

    int ntiles = (nRows + 63) >> 6;
    for (int t = blockIdx.x; t < ntiles; t += gridDim.x) {
        __syncthreads();
        int row0 = t << 6;
        // stage A tile as fp16 (2 features per thread)
        for (int i = tid; i < 64 * 64; i += 256) {
            int r = i >> 6, f = (i & 63) * 2;
            int row = row0 + r;
            __half2 v;
            if (row < nRows) {
                if (IN_HALF) {
                    v = *(const __half2*)((const __half*)Av + row * D + f);
                } else {
                    float2 x = *(const float2*)((const float*)Av + row * D + f);
                    v = __floats2half2_rn(x.x, x.y);
                }
            } else {
                v = __floats2half2_rn(0.f, 0.f);
            }
            *(__half2*)&As[r * BP + f] = v;
        }
        __syncthreads();

        float acc[8][4];
#pragma unroll
        for (int ns = 0; ns < 8; ns++)
#pragma unroll
            for (int c = 0; c < 4; c++) acc[ns][c] = 0.f;

#pragma unroll
        for (int kb = 0; kb < 8; kb++) {
            uint32_t a0, a1, a2, a3;
            ldm_x4(a0, a1, a2, a3, a_addr0 + kb * 16 * 2);
#pragma unroll
            for (int j = 0; j < 4; j++) {
                uint32_t b0, b1, b2r, b3r;
                uint32_t baddr = wt_base + ((b_row + j * 16) * BP + b_k0 + kb * 16) * 2;
                ldm_x4(b0, b1, b2r, b3r, baddr);
                mma_f16(acc[2*j][0], acc[2*j][1], acc[2*j][2], acc[2*j][3],
                        a0, a1, a2, a3, b0, b1);
                mma_f16(acc[2*j+1][0], acc[2*j+1][1], acc[2*j+1][2], acc[2*j+1][3],
                        a0, a1, a2, a3, b2r, b3r);
            }
        }

        int r0 = row0 + m0 + grp;
        int r1 = r0 + 8;
        float s0 = 1.f, s1 = 1.f;
        if (scale) {
            if (r0 < nRows) s0 = scale[r0];
            if (r1 < nRows) s1 = scale[r1];
        }
#pragma unroll
        for (int ns = 0; ns < 8; ns++) {
            int col = nbase + ns * 8 + tig * 2;
            if (r0 < nRows)
                *(__half2*)&C[r0 * D + col] = __floats2half2_rn(acc[ns][0] * s0, acc[ns][1] * s0);
            if (r1 < nRows)
                *(__half2*)&C[r1 * D + col] = __floats2half2_rn(acc[ns][2] * s1, acc[ns][3] * s1);
        }
    }
}

// ---------------- SpMM aggregation (fp16 rows, fp32 accumulate) ----------------
// f[i] = relu(dinv[i]*(sum_nbr Hs[j] + Hs[i]) + b), one node per 64-thread block
__global__ __launch_bounds__(64)
void spmm_kernel(const __half2* __restrict__ H2, const float* __restrict__ b,
                 __half2* __restrict__ fout) {
    int i = blockIdx.x;
    int tid = threadIdx.x;   // 0..63, feature pair
    __shared__ int sc[64];
    int start = g_rowptr[i], end = g_rowptr[i + 1];

    float2 v = __half22float2(H2[i * 64 + tid]);   // self-loop term
    float a0x = v.x, a0y = v.y;
    float a1x = 0.f, a1y = 0.f, a2x = 0.f, a2y = 0.f, a3x = 0.f, a3y = 0.f;

    for (int base = start; base < end; base += 64) {
        int m = end - base; if (m > 64) m = 64;
        if (tid < m) sc[tid] = g_col[base + tid];
        __syncthreads();
        int j = 0;
        for (; j + 4 <= m; j += 4) {
            float2 v0 = __half22float2(H2[sc[j]     * 64 + tid]);
            float2 v1 = __half22float2(H2[sc[j + 1] * 64 + tid]);
            float2 v2 = __half22float2(H2[sc[j + 2] * 64 + tid]);
            float2 v3 = __half22float2(H2[sc[j + 3] * 64 + tid]);
            a0x += v0.x; a0y += v0.y;
            a1x += v1.x; a1y += v1.y;
            a2x += v2.x; a2y += v2.y;
            a3x += v3.x; a3y += v3.y;
        }
        for (; j < m; j++) {
            float2 v0 = __half22float2(H2[sc[j] * 64 + tid]);
            a0x += v0.x; a0y += v0.y;
        }
        __syncthreads();
    }
    float ax = (a0x + a1x) + (a2x + a3x);
    float ay = (a0y + a1y) + (a2y + a3y);
    float di = g_dinv[i];
    float rx = fmaxf(fmaf(di, ax, b[2 * tid]),     0.f);
    float ry = fmaxf(fmaf(di, ay, b[2 * tid + 1]), 0.f);
    fout[i * 64 + tid] = __floats2half2_rn(rx, ry);
}

// ---------------- fused edge MLP (tensor-core fp16 mma) ----------------
// h1 = relu(G[s]-G[d]+bm1); h2 = relu(h1@Wm2+bm2); out = sigmoid(h2.wm3 + bm3)
#define SMEM_E_BYTES (128*BP*2 + 64*BP*2 + 3*512 + 512 + 512)

__global__ __launch_bounds__(256)
void edge_kernel(const __half* __restrict__ G, const int* __restrict__ ei,
                 const float* __restrict__ bm1, const float* __restrict__ Wm2,
                 const float* __restrict__ bm2, const float* __restrict__ Wm3,
                 const float* __restrict__ bm3, float* __restrict__ out) {
    extern __shared__ char smraw[];
    __half* Wt  = (__half*)smraw;                       // [128][BP]
    __half* h1s = (__half*)(smraw + 128 * BP * 2);      // [64][BP]
    float* sb1     = (float*)(smraw + 128*BP*2 + 64*BP*2);
    float* sb2     = sb1 + 128;
    float* sw3     = sb2 + 128;
    float* partial = sw3 + 128;                         // [64][2]
    int*   ssd     = (int*)(partial + 128);             // 128 ints

    int tid = threadIdx.x;
    for (int i = tid; i < D * D; i += 256) {
        int k = i >> 7, n = i & 127;
        Wt[n * BP + k] = __float2half(Wm2[i]);
    }
    if (tid < 128) { sb1[tid] = bm1[tid]; sb2[tid] = bm2[tid]; sw3[tid] = Wm3[tid]; }
    __syncthreads();
    float b3 = bm3[0];

    uint32_t wt_base = (uint32_t)__cvta_generic_to_shared(Wt);
    uint32_t h1_base = (uint32_t)__cvta_generic_to_shared(h1s);

    int warp = tid >> 5, l = tid & 31;
    int m0    = (warp & 3) * 16;
    int nbase = (warp >> 2) * 64;
    int nh    = warp >> 2;
    int grp = l >> 2, tig = l & 3;
    uint32_t a_addr0 = h1_base + ((m0 + (l & 15)) * BP + (l >> 4) * 8) * 2;
    int lr = l & 7, g8 = l >> 3;
    uint32_t b_row = nbase + (g8 >> 1) * 8 + lr;
    uint32_t b_k0  = (g8 & 1) * 8;

    const int ntiles = N_EDGES / 64;  // 25000 exactly

    for (int t = blockIdx.x; t < ntiles; t += gridDim.x) {
        __syncthreads();
        int e0 = t << 6;
        if (tid < 128) ssd[tid] = ei[2 * e0 + tid];
        __syncthreads();

        // build h1 tile in fp16 (4 features per thread via 8B gathers)
        for (int i = tid; i < 64 * 32; i += 256) {
            int e = i >> 5, q = (i & 31) * 4;
            int s = ssd[2 * e], d = ssd[2 * e + 1];
            uint2 us = *(const uint2*)&G[s * D + q];
            uint2 ud = *(const uint2*)&G[d * D + q];
            float2 s0 = __half22float2(*(__half2*)&us.x);
            float2 s1 = __half22float2(*(__half2*)&us.y);
            float2 d0 = __half22float2(*(__half2*)&ud.x);
            float2 d1 = __half22float2(*(__half2*)&ud.y);
            float v0 = fmaxf(s0.x - d0.x + sb1[q],     0.f);
            float v1 = fmaxf(s0.y - d0.y + sb1[q + 1], 0.f);
            float v2 = fmaxf(s1.x - d1.x + sb1[q + 2], 0.f);
            float v3 = fmaxf(s1.y - d1.y + sb1[q + 3], 0.f);
            *(__half2*)&h1s[e * BP + q]     = __floats2half2_rn(v0, v1);
            *(__half2*)&h1s[e * BP + q + 2] = __floats2half2_rn(v2, v3);
        }
        __syncthreads();

        float acc[8][4];
#pragma unroll
        for (int ns = 0; ns < 8; ns++)
#pragma unroll
            for (int c = 0; c < 4; c++) acc[ns][c] = 0.f;

#pragma unroll
        for (int kb = 0; kb < 8; kb++) {
            uint32_t a0, a1, a2, a3;
            ldm_x4(a0, a1, a2, a3, a_addr0 + kb * 16 * 2);
#pragma unroll
            for (int j = 0; j < 4; j++) {
                uint32_t b0, b1, b2r, b3r;
                uint32_t baddr = wt_base + ((b_row + j * 16) * BP + b_k0 + kb * 16) * 2;
                ldm_x4(b0, b1, b2r, b3r, baddr);
                mma_f16(acc[2*j][0], acc[2*j][1], acc[2*j][2], acc[2*j][3],
                        a0, a1, a2, a3, b0, b1);
                mma_f16(acc[2*j+1][0], acc[2*j+1][1], acc[2*j+1][2], acc[2*j+1][3],
                        a0, a1, a2, a3, b2r, b3r);
            }
        }

        // epilogue: relu + dot with wm3, quad reduce, cross-half reduce, sigmoid
        float p0 = 0.f, p1 = 0.f;
#pragma unroll
        for (int ns = 0; ns < 8; ns++) {
            int c0 = nbase + ns * 8 + tig * 2;
            int c1 = c0 + 1;
            p0 = fmaf(fmaxf(acc[ns][0] + sb2[c0], 0.f), sw3[c0], p0);
            p0 = fmaf(fmaxf(acc[ns][1] + sb2[c1], 0.f), sw3[c1], p0);
            p1 = fmaf(fmaxf(acc[ns][2] + sb2[c0], 0.f), sw3[c0], p1);
            p1 = fmaf(fmaxf(acc[ns][3] + sb2[c1], 0.f), sw3[c1], p1);
        }
        p0 += __shfl_xor_sync(0xffffffffu, p0, 1);
        p0 += __shfl_xor_sync(0xffffffffu, p0, 2);
        p1 += __shfl_xor_sync(0xffffffffu, p1, 1);
        p1 += __shfl_xor_sync(0xffffffffu, p1, 2);
        if (tig == 0) {
            partial[(m0 + grp) * 2 + nh]     = p0;
            partial[(m0 + grp + 8) * 2 + nh] = p1;
        }
        __syncthreads();
        if (tid < 64) {
            float z = partial[tid * 2] + partial[tid * 2 + 1] + b3;
            out[e0 + tid] = 1.0f / (1.0f + expf(-z));
        }
    }
}

// ---------------- launch ----------------
extern "C" void kernel_launch(void* const* d_in, const int* in_sizes, int n_in,
                              void* d_out, int out_size) {
    const float* x   = (const float*)d_in[0];
    const int*   ei  = (const int*)d_in[1];
    const float* W1  = (const float*)d_in[2];
    const float* b1  = (const float*)d_in[3];
    const float* W2  = (const float*)d_in[4];
    const float* b2  = (const float*)d_in[5];
    const float* Wm1 = (const float*)d_in[6];
    const float* bm1 = (const float*)d_in[7];
    const float* Wm2 = (const float*)d_in[8];
    const float* bm2 = (const float*)d_in[9];
    const float* Wm3 = (const float*)d_in[10];
    const float* bm3 = (const float*)d_in[11];
    float* out = (float*)d_out;

    void *bufA, *bufB, *dinvp;
    cudaGetSymbolAddress(&bufA, g_bufA);
    cudaGetSymbolAddress(&bufB, g_bufB);
    cudaGetSymbolAddress(&dinvp, g_dinv);
    __half* hA = (__half*)bufA;
    __half* hB = (__half*)bufB;
    const float* dinv = (const float*)dinvp;

    cudaFuncSetAttribute(gemm_tc_kernel<0>, cudaFuncAttributeMaxDynamicSharedMemorySize, SMEM_G_BYTES);
    cudaFuncSetAttribute(gemm_tc_kernel<1>, cudaFuncAttributeMaxDynamicSharedMemorySize, SMEM_G_BYTES);
    cudaFuncSetAttribute(edge_kernel, cudaFuncAttributeMaxDynamicSharedMemorySize, SMEM_E_BYTES);

    const int GRID  = 296;
    const int GRIDE = 444;

    // CSR build + degrees
    zero_cnt_kernel<<<(N_NODES + 255) / 256, 256>>>();
    count_kernel<<<(N_EDGES + 255) / 256, 256>>>((const int2*)ei);
    scan_block_kernel<<<(N_NODES + 1023) / 1024, 1024>>>();
    scan_bsum_kernel<<<1, 32>>>((N_NODES + 1023) / 1024);
    scan_fix_kernel<<<(N_NODES + 255) / 256, 256>>>();
    fill_kernel<<<(N_EDGES + 255) / 256, 256>>>((const int2*)ei);

    // GCN layer 1: Hs1 = dinv * (x @ W1); f1 = relu(dinv*(agg+self) + b1)
    gemm_tc_kernel<0><<<GRID, 256, SMEM_G_BYTES>>>(x, W1, hA, dinv, N_NODES);
    spmm_kernel<<<N_NODES, 64>>>((const __half2*)hA, b1, (__half2*)hB);

    // GCN layer 2
    gemm_tc_kernel<1><<<GRID, 256, SMEM_G_BYTES>>>(hB, W2, hA, dinv, N_NODES);
    spmm_kernel<<<N_NODES, 64>>>((const __half2*)hA, b2, (__half2*)hB);

    // G = f2 @ Wm1  (factored edge-MLP layer 1)
    gemm_tc_kernel<1><<<GRID, 256, SMEM_G_BYTES>>>(hB, Wm1, hA, nullptr, N_NODES);

    // fused edge MLP on tensor cores
    edge_kernel<<<GRIDE, 256, SMEM_E_BYTES>>>(hA, ei, bm1, Wm2, bm2, Wm3, bm3, out);
}